// round 13
// baseline (speedup 1.0000x reference)
#include <cuda_runtime.h>
#include <cuda_fp16.h>
#include <cstdint>

#define CB 8
#define CN 4096
#define CD 512
#define CH 8
#define CM 256
#define CDH 64
#define CL 16
#define CITERS 6
#define CSCALE 0.125f
#define CP 1536

// ---------------- scratch (all internal tensors fp16) -----------------------
__device__ __half g_xh  [CB * CN * CD];
__device__ __half g_wqh [CD * CP];
__device__ __half g_woh [CD * CD];
__device__ __half g_qkv [CB * CN * CP];
__device__ __half g_ql  [CB * CH * CM * CDH];
__device__ __half g_kl  [CB * CH * CM * CDH];
__device__ __half g_a2  [CB * CH * CM * CM];
__device__ __half g_z0  [CB * CH * CM * CM];
__device__ __half g_z1  [CB * CH * CM * CM];
__device__ __half g_xz  [CB * CH * CM * CM];
__device__ __half g_tt  [CB * CH * CM * CM];
__device__ __half g_uu  [CB * CH * CM * CM];
__device__ __half g_t2  [CB * CH * CM * CDH];
__device__ __half g_zt2 [CB * CH * CM * CDH];
__device__ __half g_oh  [CB * CN * CD];
__device__ unsigned g_scal[2];

// ---------------- helpers ----------------------------------------------------
__device__ __forceinline__ uint32_t h2pack(float lo, float hi) {
    __half2 h = __floats2half2_rn(lo, hi);
    return *reinterpret_cast<uint32_t*>(&h);
}

__device__ __forceinline__ void mma_f16(float* c, const uint32_t* a, const uint32_t* b) {
    asm volatile(
        "mma.sync.aligned.m16n8k16.row.col.f32.f16.f16.f32 "
        "{%0,%1,%2,%3}, {%4,%5,%6,%7}, {%8,%9}, {%0,%1,%2,%3};\n"
        : "+f"(c[0]), "+f"(c[1]), "+f"(c[2]), "+f"(c[3])
        : "r"(a[0]), "r"(a[1]), "r"(a[2]), "r"(a[3]), "r"(b[0]), "r"(b[1]));
}

__device__ __forceinline__ void cp16(void* smem_dst, const void* gsrc) {
    uint32_t d = (uint32_t)__cvta_generic_to_shared(smem_dst);
    asm volatile("cp.async.cg.shared.global [%0], [%1], 16;\n" :: "r"(d), "l"(gsrc));
}

#define LDMX4(r0, r1, r2, r3, addr) \
    asm volatile("ldmatrix.sync.aligned.m8n8.x4.shared.b16 {%0,%1,%2,%3}, [%4];" \
                 : "=r"(r0), "=r"(r1), "=r"(r2), "=r"(r3) : "r"(addr))
#define LDMX4T(r0, r1, r2, r3, addr) \
    asm volatile("ldmatrix.sync.aligned.m8n8.x4.trans.shared.b16 {%0,%1,%2,%3}, [%4];" \
                 : "=r"(r0), "=r"(r1), "=r"(r2), "=r"(r3) : "r"(addr))

// ---------------- fp16 tensor-core batched GEMM (3-stage, dyn smem) ---------
// KT=32. A stride 56 halfs (112B, ldmatrix conflict-free).
// MODE: 0=plain(C half), 1=+bias final (C float), 2=C and D=dc*I-C, 3=only D.
#define KT 32
#define AST 56

template <int BM, int BN, bool TRANSB>
constexpr int gemm_smem_h() {
    return 3 * BM * AST * 2 + (TRANSB ? 3 * BN * AST * 2 : 3 * KT * (BN + 8) * 2);
}

template <int BM, int BN, int WM, int WN, bool TRANSB, int MODE>
__global__ __launch_bounds__(256)
void gemm_h(const __half* __restrict__ A, const __half* __restrict__ B,
            void* __restrict__ Cv, __half* __restrict__ D,
            const float* __restrict__ bias,
            int Kr, int lda, int ldb, int ldc,
            size_t sA1, size_t sA2, size_t sB1, size_t sB2,
            size_t sC1, size_t sC2, float alpha, float dc) {
    constexpr int MF = WM / 16;
    constexpr int NF = WN / 8;
    constexpr int WARPS_N = BN / WN;
    constexpr int BST = BN + 8;   // !TRANSB B stride

    int z = blockIdx.z;
    int zh = z & (CH - 1), zb = z >> 3;
    A += (size_t)zb * sA2 + (size_t)zh * sA1;
    B += (size_t)zb * sB2 + (size_t)zh * sB1;
    __half* C = (__half*)Cv;
    float* Cf = (float*)Cv;
    if (MODE == 1) Cf += (size_t)zb * sC2 + (size_t)zh * sC1;
    else           C  += (size_t)zb * sC2 + (size_t)zh * sC1;
    if (MODE >= 2) D += (size_t)zb * sC2 + (size_t)zh * sC1;

    extern __shared__ __half smh[];
    __half* AsB = smh;                      // [3][BM][AST]
    __half* BsB = smh + 3 * BM * AST;
    uint32_t as_u32 = (uint32_t)__cvta_generic_to_shared(AsB);
    uint32_t bs_u32 = (uint32_t)__cvta_generic_to_shared(BsB);

    int tid = threadIdx.x;
    int m0 = blockIdx.y * BM, n0 = blockIdx.x * BN;
    int wid = tid >> 5, lane = tid & 31;
    int wm = (wid / WARPS_N) * WM;
    int wn = (wid % WARPS_N) * WN;
    int r = lane >> 2, cq = lane & 3;
    int l15 = lane & 15, lhi8 = (lane >> 4) << 3;

    float acc[MF][NF][4] = {};

    auto loadA = [&](int k0, int buf) {
        constexpr int CH8 = BM * KT / 8;
        __half* As = AsB + buf * BM * AST;
#pragma unroll
        for (int c = tid; c < CH8; c += 256) {
            int row = c >> 2, col8 = (c & 3) << 3;
            cp16(&As[row * AST + col8], A + (size_t)(m0 + row) * lda + k0 + col8);
        }
    };
    auto loadB = [&](int k0, int buf) {
        if (TRANSB) {
            constexpr int CH8 = BN * KT / 8;
            __half* Bs = BsB + buf * BN * AST;
#pragma unroll
            for (int c = tid; c < CH8; c += 256) {
                int row = c >> 2, col8 = (c & 3) << 3;
                cp16(&Bs[row * AST + col8], B + (size_t)(n0 + row) * ldb + k0 + col8);
            }
        } else {
            constexpr int CPR = BN / 8;
            constexpr int CH8 = KT * CPR;
            __half* Bs = BsB + buf * KT * BST;
#pragma unroll
            for (int c = tid; c < CH8; c += 256) {
                int row = c / CPR, col8 = (c % CPR) << 3;
                cp16(&Bs[row * BST + col8], B + (size_t)(k0 + row) * ldb + n0 + col8);
            }
        }
    };

    int ntile = Kr / KT;
    loadA(0, 0); loadB(0, 0);
    asm volatile("cp.async.commit_group;\n");
    if (ntile > 1) {
        loadA(KT, 1); loadB(KT, 1);
        asm volatile("cp.async.commit_group;\n");
    }

    for (int t = 0; t < ntile; t++) {
        int buf = t % 3;
        if (t + 2 < ntile) {
            loadA((t + 2) * KT, (t + 2) % 3);
            loadB((t + 2) * KT, (t + 2) % 3);
            asm volatile("cp.async.commit_group;\n");
        }
        int rem = ntile - 1 - t;
        if (rem >= 2)      asm volatile("cp.async.wait_group 2;\n");
        else if (rem == 1) asm volatile("cp.async.wait_group 1;\n");
        else               asm volatile("cp.async.wait_group 0;\n");
        __syncthreads();

        uint32_t a_u = as_u32 + (uint32_t)(buf * BM * AST) * 2;
        uint32_t b_u = TRANSB ? bs_u32 + (uint32_t)(buf * BN * AST) * 2
                              : bs_u32 + (uint32_t)(buf * KT * BST) * 2;
#pragma unroll
        for (int kg = 0; kg < KT; kg += 16) {
            uint32_t afr[MF][4], bfr[NF][2];
#pragma unroll
            for (int mf = 0; mf < MF; mf++) {
                uint32_t addr = a_u + (uint32_t)((wm + mf * 16 + l15) * AST + kg + lhi8) * 2;
                LDMX4(afr[mf][0], afr[mf][1], afr[mf][2], afr[mf][3], addr);
            }
#pragma unroll
            for (int pr = 0; pr < NF / 2; pr++) {
                if (TRANSB) {
                    // [N,K] rows: x4 over n16 -> nf_lo={r0,r2}, nf_hi={r1,r3}
                    uint32_t addr = b_u + (uint32_t)((wn + pr * 16 + l15) * AST + kg + lhi8) * 2;
                    LDMX4(bfr[2 * pr][0], bfr[2 * pr + 1][0],
                          bfr[2 * pr][1], bfr[2 * pr + 1][1], addr);
                } else {
                    // [K,N]: x4.trans over k16 x n16 -> nf_lo={r0,r1}, nf_hi={r2,r3}
                    uint32_t addr = b_u + (uint32_t)((kg + l15) * BST + wn + pr * 16 + lhi8) * 2;
                    LDMX4T(bfr[2 * pr][0], bfr[2 * pr][1],
                           bfr[2 * pr + 1][0], bfr[2 * pr + 1][1], addr);
                }
            }
#pragma unroll
            for (int mf = 0; mf < MF; mf++)
#pragma unroll
                for (int nf = 0; nf < NF; nf++)
                    mma_f16(acc[mf][nf], afr[mf], bfr[nf]);
        }
        __syncthreads();
    }

#pragma unroll
    for (int mf = 0; mf < MF; mf++) {
#pragma unroll
        for (int h = 0; h < 2; h++) {
            int row = m0 + wm + mf * 16 + r + h * 8;
#pragma unroll
            for (int nf = 0; nf < NF; nf++) {
                int col = n0 + wn + nf * 8 + 2 * cq;
                float v0 = acc[mf][nf][2 * h] * alpha;
                float v1 = acc[mf][nf][2 * h + 1] * alpha;
                if (MODE == 1) {
                    v0 += bias[col]; v1 += bias[col + 1];
                    *(float2*)&Cf[(size_t)row * ldc + col] = make_float2(v0, v1);
                } else if (MODE <= 2) {
                    *(uint32_t*)&C[(size_t)row * ldc + col] = h2pack(v0, v1);
                }
                if (MODE >= 2) {
                    float d0 = (row == col     ? dc : 0.f) - v0;
                    float d1 = (row == col + 1 ? dc : 0.f) - v1;
                    *(uint32_t*)&D[(size_t)row * ldc + col] = h2pack(d0, d1);
                }
            }
        }
    }
}

// ---------------- fp16 flash attention --------------------------------------
template <int NW>
__global__ __launch_bounds__(NW * 32, 2)
void flash_h(const __half* __restrict__ Q, int ldq, size_t sQ1, size_t sQ2,
             const __half* __restrict__ K, int ldk, size_t sK1, size_t sK2,
             const __half* __restrict__ V, int ldv, size_t sV1, size_t sV2,
             __half* __restrict__ O, int ldo, size_t sO1, size_t sO2,
             int nkeys, float alpha) {
    extern __shared__ __half smh[];
    __half* KsB = smh;                 // [2][64][72]
    __half* VsB = smh + 2 * 64 * 72;
    constexpr int NT = NW * 32;
    uint32_t ks_u32 = (uint32_t)__cvta_generic_to_shared(KsB);
    uint32_t vs_u32 = (uint32_t)__cvta_generic_to_shared(VsB);

    int z = blockIdx.z;
    int zh = z & 7, zb = z >> 3;
    Q += (size_t)zb * sQ2 + (size_t)zh * sQ1;
    K += (size_t)zb * sK2 + (size_t)zh * sK1;
    V += (size_t)zb * sV2 + (size_t)zh * sV1;
    O += (size_t)zb * sO2 + (size_t)zh * sO1;

    int tid = threadIdx.x, wid = tid >> 5, lane = tid & 31;
    int r = lane >> 2, cq = lane & 3;
    int l15 = lane & 15, lhi8 = (lane >> 4) << 3;
    int qbase = blockIdx.x * (NW * 16);
    int wm = wid * 16;

    uint32_t aq[4][4];
    {
        const __half* q0 = Q + (size_t)(qbase + wm + r) * ldq;
        const __half* q1 = Q + (size_t)(qbase + wm + r + 8) * ldq;
#pragma unroll
        for (int kt = 0; kt < 4; kt++) {
            aq[kt][0] = *(const uint32_t*)&q0[kt * 16 + 2 * cq];
            aq[kt][1] = *(const uint32_t*)&q1[kt * 16 + 2 * cq];
            aq[kt][2] = *(const uint32_t*)&q0[kt * 16 + 8 + 2 * cq];
            aq[kt][3] = *(const uint32_t*)&q1[kt * 16 + 8 + 2 * cq];
        }
    }

    float m0 = -1e30f, m1 = -1e30f, l0 = 0.f, l1 = 0.f;
    float acc_o[8][4] = {};

    auto loadKV = [&](int key0, int buf) {
#pragma unroll
        for (int c = tid; c < 512; c += NT) {
            int row = c >> 3, col8 = (c & 7) << 3;
            cp16(&KsB[buf * 64 * 72 + row * 72 + col8], K + (size_t)(key0 + row) * ldk + col8);
            cp16(&VsB[buf * 64 * 72 + row * 72 + col8], V + (size_t)(key0 + row) * ldv + col8);
        }
    };

    int nchunks = nkeys >> 6;
    loadKV(0, 0);
    asm volatile("cp.async.commit_group;\n");

    for (int ch = 0; ch < nchunks; ch++) {
        int buf = ch & 1;
        if (ch + 1 < nchunks) {
            loadKV((ch + 1) * 64, buf ^ 1);
            asm volatile("cp.async.commit_group;\n");
            asm volatile("cp.async.wait_group 1;\n");
        } else {
            asm volatile("cp.async.wait_group 0;\n");
        }
        __syncthreads();

        uint32_t kb_u = ks_u32 + (uint32_t)(buf * 64 * 72) * 2;
        uint32_t vb_u = vs_u32 + (uint32_t)(buf * 64 * 72) * 2;

        // S = Q @ K^T (K rows = keys, K-major: x4 over key16 -> 2 nf per load)
        float p[8][4];
#pragma unroll
        for (int nf = 0; nf < 8; nf++)
            p[nf][0] = p[nf][1] = p[nf][2] = p[nf][3] = 0.f;
#pragma unroll
        for (int kt = 0; kt < 4; kt++) {
#pragma unroll
            for (int pr = 0; pr < 4; pr++) {
                uint32_t b2[2][2];
                uint32_t addr = kb_u + (uint32_t)((pr * 16 + l15) * 72 + kt * 16 + lhi8) * 2;
                LDMX4(b2[0][0], b2[1][0], b2[0][1], b2[1][1], addr);
                mma_f16(p[2 * pr],     aq[kt], b2[0]);
                mma_f16(p[2 * pr + 1], aq[kt], b2[1]);
            }
        }
        float mx0 = -1e30f, mx1 = -1e30f;
#pragma unroll
        for (int nf = 0; nf < 8; nf++) {
            p[nf][0] *= alpha; p[nf][1] *= alpha; p[nf][2] *= alpha; p[nf][3] *= alpha;
            mx0 = fmaxf(mx0, fmaxf(p[nf][0], p[nf][1]));
            mx1 = fmaxf(mx1, fmaxf(p[nf][2], p[nf][3]));
        }
        mx0 = fmaxf(mx0, __shfl_xor_sync(~0u, mx0, 1));
        mx0 = fmaxf(mx0, __shfl_xor_sync(~0u, mx0, 2));
        mx1 = fmaxf(mx1, __shfl_xor_sync(~0u, mx1, 1));
        mx1 = fmaxf(mx1, __shfl_xor_sync(~0u, mx1, 2));
        float nm0 = fmaxf(m0, mx0), nm1 = fmaxf(m1, mx1);
        float f0 = __expf(m0 - nm0), f1 = __expf(m1 - nm1);
        m0 = nm0; m1 = nm1;
        float s0 = 0.f, s1 = 0.f;
#pragma unroll
        for (int nf = 0; nf < 8; nf++) {
            p[nf][0] = __expf(p[nf][0] - m0);
            p[nf][1] = __expf(p[nf][1] - m0);
            p[nf][2] = __expf(p[nf][2] - m1);
            p[nf][3] = __expf(p[nf][3] - m1);
            s0 += p[nf][0] + p[nf][1];
            s1 += p[nf][2] + p[nf][3];
        }
        s0 += __shfl_xor_sync(~0u, s0, 1); s0 += __shfl_xor_sync(~0u, s0, 2);
        s1 += __shfl_xor_sync(~0u, s1, 1); s1 += __shfl_xor_sync(~0u, s1, 2);
        l0 = l0 * f0 + s0;
        l1 = l1 * f1 + s1;
#pragma unroll
        for (int nf = 0; nf < 8; nf++) {
            acc_o[nf][0] *= f0; acc_o[nf][1] *= f0;
            acc_o[nf][2] *= f1; acc_o[nf][3] *= f1;
        }

        // O += P @ V  (V via x4.trans over k16 x n16 -> 2 nf per load)
#pragma unroll
        for (int kt = 0; kt < 4; kt++) {
            uint32_t a[4];
            a[0] = h2pack(p[2 * kt][0],     p[2 * kt][1]);
            a[1] = h2pack(p[2 * kt][2],     p[2 * kt][3]);
            a[2] = h2pack(p[2 * kt + 1][0], p[2 * kt + 1][1]);
            a[3] = h2pack(p[2 * kt + 1][2], p[2 * kt + 1][3]);
#pragma unroll
            for (int pr = 0; pr < 4; pr++) {
                uint32_t b2[2][2];
                uint32_t addr = vb_u + (uint32_t)((kt * 16 + l15) * 72 + pr * 16 + lhi8) * 2;
                LDMX4T(b2[0][0], b2[0][1], b2[1][0], b2[1][1], addr);
                mma_f16(acc_o[2 * pr],     a, b2[0]);
                mma_f16(acc_o[2 * pr + 1], a, b2[1]);
            }
        }
        __syncthreads();
    }

    float inv0 = 1.f / l0, inv1 = 1.f / l1;
    int row0 = qbase + wm + r, row1 = row0 + 8;
#pragma unroll
    for (int nf = 0; nf < 8; nf++) {
        int col = nf * 8 + 2 * cq;
        *(uint32_t*)&O[(size_t)row0 * ldo + col] =
            h2pack(acc_o[nf][0] * inv0, acc_o[nf][1] * inv0);
        *(uint32_t*)&O[(size_t)row1 * ldo + col] =
            h2pack(acc_o[nf][2] * inv1, acc_o[nf][3] * inv1);
    }
}

// ---------------- fp32 -> fp16 input conversion ------------------------------
__global__ void f2h_k(const float* __restrict__ s, __half* __restrict__ d) {
    int i = blockIdx.x * blockDim.x + threadIdx.x;
    float4 v = ((const float4*)s)[i];
    uint2 o;
    o.x = h2pack(v.x, v.y);
    o.y = h2pack(v.z, v.w);
    ((uint2*)d)[i] = o;
}

// ---------------- landmarks --------------------------------------------------
__global__ void landmark_k() {
    int idx = blockIdx.x * blockDim.x + threadIdx.x;
    if (idx >= CB * CH * CM * CDH) return;
    int d = idx & 63;
    int m = (idx >> 6) & (CM - 1);
    int h = (idx >> 14) & (CH - 1);
    int b = idx >> 17;
    const __half* base = g_qkv + ((size_t)(b * CN + m * CL)) * CP + h * CDH + d;
    float sq = 0.f, sk = 0.f;
#pragma unroll
    for (int j = 0; j < CL; j++) {
        sq += __half2float(base[(size_t)j * CP]);
        sk += __half2float(base[(size_t)j * CP + CD]);
    }
    g_ql[idx] = __float2half(sq * (CSCALE / CL));
    g_kl[idx] = __float2half(sk * (1.0f / CL));
}

// ---------------- softmax (half rows of 256) ---------------------------------
__global__ void softmax256_k(__half* __restrict__ data) {
    int row = blockIdx.x * 8 + (threadIdx.x >> 5);
    int lane = threadIdx.x & 31;
    uint4* pv = (uint4*)(data + (size_t)row * 256);
    uint4 u = pv[lane];
    __half2* hs = (__half2*)&u;
    float f[8];
#pragma unroll
    for (int i = 0; i < 4; i++) {
        float2 ff = __half22float2(hs[i]);
        f[2 * i] = ff.x; f[2 * i + 1] = ff.y;
    }
    float mx = -3.4e38f;
#pragma unroll
    for (int i = 0; i < 8; i++) mx = fmaxf(mx, f[i]);
#pragma unroll
    for (int s = 16; s > 0; s >>= 1) mx = fmaxf(mx, __shfl_xor_sync(~0u, mx, s));
    float sum = 0.f;
#pragma unroll
    for (int i = 0; i < 8; i++) { f[i] = __expf(f[i] - mx); sum += f[i]; }
#pragma unroll
    for (int s = 16; s > 0; s >>= 1) sum += __shfl_xor_sync(~0u, sum, s);
    float inv = 1.f / sum;
#pragma unroll
    for (int i = 0; i < 4; i++)
        hs[i] = __floats2half2_rn(f[2 * i] * inv, f[2 * i + 1] * inv);
    pv[lane] = u;
}

// ---------------- pinv scaling ---------------------------------------------
__global__ void pinv_scal_init() { if (threadIdx.x < 2) g_scal[threadIdx.x] = 0u; }

__global__ void pinv_scal_k() {
    const __half* a = g_a2 + (size_t)blockIdx.x * CM * CM;
    int t = threadIdx.x;
    float cs = 0.f, rs = 0.f;
    for (int i = 0; i < CM; i++) {
        cs += fabsf(__half2float(a[i * CM + t]));
        rs += fabsf(__half2float(a[t * CM + i]));
    }
    __shared__ float sh[256];
    sh[t] = rs; __syncthreads();
    for (int s = 128; s > 0; s >>= 1) { if (t < s) sh[t] = fmaxf(sh[t], sh[t + s]); __syncthreads(); }
    if (t == 0) atomicMax(&g_scal[0], __float_as_uint(sh[0]));
    __syncthreads();
    sh[t] = cs; __syncthreads();
    for (int s = 128; s > 0; s >>= 1) { if (t < s) sh[t] = fmaxf(sh[t], sh[t + s]); __syncthreads(); }
    if (t == 0) atomicMax(&g_scal[1], __float_as_uint(sh[0]));
}

__global__ void zinit_k() {
    int idx = blockIdx.x * blockDim.x + threadIdx.x;
    if (idx >= CB * CH * CM * CM) return;
    float inv = 1.f / (__uint_as_float(g_scal[0]) * __uint_as_float(g_scal[1]));
    int z = idx >> 16;
    int im = idx & 65535;
    int i = im >> 8, j = im & 255;
    g_z0[(size_t)z * 65536 + j * 256 + i] = __float2half(__half2float(g_a2[idx]) * inv);
}

// ---------------- host ------------------------------------------------------
extern "C" void kernel_launch(void* const* d_in, const int* in_sizes, int n_in,
                              void* d_out, int out_size) {
    const float* x     = (const float*)d_in[0];
    const float* w_qkv = (const float*)d_in[1];
    const float* w_out = (const float*)d_in[2];
    const float* b_out = (const float*)d_in[3];
    float* out = (float*)d_out;

    constexpr int SM_NN   = gemm_smem_h<128, 128, false>();
    constexpr int SM_N64  = gemm_smem_h<128, 64, false>();
    constexpr int SM_NT64 = gemm_smem_h<128, 64, true>();
    const int FLASH_SMEM = 2 * 2 * 64 * 72 * 2;

    static __half *p_xh = nullptr, *p_wqh, *p_woh, *p_qkv, *p_ql, *p_kl, *p_a2,
                  *p_z0, *p_z1, *p_xz, *p_tt, *p_uu, *p_t2, *p_zt2, *p_oh;
    static cudaStream_t s1;
    static cudaEvent_t evFork, evJoin;
    if (!p_xh) {
        cudaGetSymbolAddress((void**)&p_xh,   g_xh);
        cudaGetSymbolAddress((void**)&p_wqh,  g_wqh);
        cudaGetSymbolAddress((void**)&p_woh,  g_woh);
        cudaGetSymbolAddress((void**)&p_qkv,  g_qkv);
        cudaGetSymbolAddress((void**)&p_ql,   g_ql);
        cudaGetSymbolAddress((void**)&p_kl,   g_kl);
        cudaGetSymbolAddress((void**)&p_a2,   g_a2);
        cudaGetSymbolAddress((void**)&p_z0,   g_z0);
        cudaGetSymbolAddress((void**)&p_z1,   g_z1);
        cudaGetSymbolAddress((void**)&p_xz,   g_xz);
        cudaGetSymbolAddress((void**)&p_tt,   g_tt);
        cudaGetSymbolAddress((void**)&p_uu,   g_uu);
        cudaGetSymbolAddress((void**)&p_t2,   g_t2);
        cudaGetSymbolAddress((void**)&p_zt2,  g_zt2);
        cudaGetSymbolAddress((void**)&p_oh,   g_oh);
        cudaStreamCreateWithFlags(&s1, cudaStreamNonBlocking);
        cudaEventCreateWithFlags(&evFork, cudaEventDisableTiming);
        cudaEventCreateWithFlags(&evJoin, cudaEventDisableTiming);
        cudaFuncSetAttribute(flash_h<8>, cudaFuncAttributeMaxDynamicSharedMemorySize, FLASH_SMEM);
        cudaFuncSetAttribute((const void*)gemm_h<128, 128, 64, 32, false, 0>,
                             cudaFuncAttributeMaxDynamicSharedMemorySize, SM_NN);
        cudaFuncSetAttribute((const void*)gemm_h<128, 128, 64, 32, false, 1>,
                             cudaFuncAttributeMaxDynamicSharedMemorySize, SM_NN);
        cudaFuncSetAttribute((const void*)gemm_h<128, 64, 32, 32, false, 0>,
                             cudaFuncAttributeMaxDynamicSharedMemorySize, SM_N64);
        cudaFuncSetAttribute((const void*)gemm_h<128, 64, 32, 32, false, 2>,
                             cudaFuncAttributeMaxDynamicSharedMemorySize, SM_N64);
        cudaFuncSetAttribute((const void*)gemm_h<128, 64, 32, 32, false, 3>,
                             cudaFuncAttributeMaxDynamicSharedMemorySize, SM_N64);
        cudaFuncSetAttribute((const void*)gemm_h<128, 64, 32, 32, true, 0>,
                             cudaFuncAttributeMaxDynamicSharedMemorySize, SM_NT64);
    }

    const size_t sQKVh = CDH;
    const size_t sQKVb = (size_t)CN * CP;
    const size_t sLMh  = (size_t)CM * CDH;
    const size_t sMM   = (size_t)CM * CM;
    const size_t sT2   = (size_t)CM * CDH;

    // 0) input conversion (w_out on s1)
    f2h_k<<<(CB * CN * CD) / 1024, 256>>>(x, p_xh);
    f2h_k<<<(CD * CP) / 1024, 256>>>(w_qkv, p_wqh);
    f2h_k<<<(CD * CD) / 1024, 256, 0, s1>>>(w_out, p_woh);

    // 1) qkv = x @ w_qkv
    gemm_h<128, 128, 64, 32, false, 0>
        <<<dim3(CP / 128, (CB * CN) / 128, 1), 256, SM_NN>>>(
        p_xh, p_wqh, p_qkv, nullptr, nullptr, CD, CD, CP, CP,
        0, 0, 0, 0, 0, 0, 1.f, 0.f);

    // 2) landmarks
    landmark_k<<<(CB * CH * CM * CDH) / 256, 256>>>();

    // ---- fork: F1 on s1, concurrent with pinv pipeline
    cudaEventRecord(evFork, 0);
    cudaStreamWaitEvent(s1, evFork, 0);
    flash_h<8><<<dim3(CM / 128, 1, CB * CH), 256, FLASH_SMEM, s1>>>(
        p_ql, CDH, sLMh, CH * sLMh,
        p_qkv + CD, CP, sQKVh, sQKVb,
        p_qkv + 2 * CD, CP, sQKVh, sQKVb,
        p_t2, CDH, sT2, CH * sT2,
        CN, 1.f);
    cudaEventRecord(evJoin, s1);

    // 3) sim2 = ql @ kl^T ; softmax
    gemm_h<128, 64, 32, 32, true, 0>
        <<<dim3(CM / 64, CM / 128, CB * CH), 256, SM_NT64>>>(
        p_ql, p_kl, p_a2, nullptr, nullptr, CDH, CDH, CDH, CM,
        sLMh, CH * sLMh, sLMh, CH * sLMh, sMM, CH * sMM, 1.f, 0.f);
    softmax256_k<<<(CB * CH * CM) / 8, 256>>>(p_a2);

    // 5) pinv init
    pinv_scal_init<<<1, 32>>>();
    pinv_scal_k<<<CB * CH, 256>>>();
    zinit_k<<<(CB * CH * CM * CM) / 256, 256>>>();

    // 6) Newton-Schulz iterations (L2-resident; 128x64 tiles for short launches)
    dim3 gMM(CM / 64, CM / 128, CB * CH);
    __half* zin = p_z0;
    __half* zout = p_z1;
    for (int it = 0; it < CITERS; it++) {
        gemm_h<128, 64, 32, 32, false, 2><<<gMM, 256, SM_N64>>>(
            p_a2, zin, p_xz, p_tt, nullptr, CM, CM, CM, CM,
            sMM, CH * sMM, sMM, CH * sMM, sMM, CH * sMM, 1.f, 7.f);
        gemm_h<128, 64, 32, 32, false, 3><<<gMM, 256, SM_N64>>>(
            p_xz, p_tt, nullptr, p_uu, nullptr, CM, CM, CM, CM,
            sMM, CH * sMM, sMM, CH * sMM, sMM, CH * sMM, 1.f, 15.f);
        gemm_h<128, 64, 32, 32, false, 3><<<gMM, 256, SM_N64>>>(
            p_xz, p_uu, nullptr, p_tt, nullptr, CM, CM, CM, CM,
            sMM, CH * sMM, sMM, CH * sMM, sMM, CH * sMM, 1.f, 13.f);
        gemm_h<128, 64, 32, 32, false, 0><<<gMM, 256, SM_N64>>>(
            zin, p_tt, zout, nullptr, nullptr, CM, CM, CM, CM,
            sMM, CH * sMM, sMM, CH * sMM, sMM, CH * sMM, 0.25f, 0.f);
        __half* tmp = zin; zin = zout; zout = tmp;
    }

    // ---- join: t2 ready
    cudaStreamWaitEvent(0, evJoin, 0);

    // 7) zt2 = z @ t2
    gemm_h<128, 64, 32, 32, false, 0>
        <<<dim3(1, CM / 128, CB * CH), 256, SM_N64>>>(
        zin, p_t2, p_zt2, nullptr, nullptr, CM, CM, CDH, CDH,
        sMM, CH * sMM, sT2, CH * sT2, sT2, CH * sT2, 1.f, 0.f);

    // 8) F2: oh = softmax(SCALE * q @ kl^T) @ zt2  -> [b,n,h*dh]
    flash_h<8><<<dim3(CN / 128, 1, CB * CH), 256, FLASH_SMEM>>>(
        p_qkv, CP, sQKVh, sQKVb,
        p_kl, CDH, sLMh, CH * sLMh,
        p_zt2, CDH, sT2, CH * sT2,
        p_oh, CD, (size_t)CDH, (size_t)CN * CD,
        CM, CSCALE);

    // 9) out = oh @ w_out + b_out   (fp32 output)
    gemm_h<128, 128, 64, 32, false, 1>
        <<<dim3(CD / 128, (CB * CN) / 128, 1), 256, SM_NN>>>(
        p_oh, p_woh, out, nullptr, b_out, CD, CD, CD, CD,
        0, 0, 0, 0, 0, 0, 1.f, 0.f);
}

// round 14
// speedup vs baseline: 1.0409x; 1.0409x over previous
#include <cuda_runtime.h>
#include <cuda_fp16.h>
#include <cstdint>

#define CB 8
#define CN 4096
#define CD 512
#define CH 8
#define CM 256
#define CDH 64
#define CL 16
#define CITERS 6
#define CSCALE 0.125f
#define CP 1536

// ---------------- scratch (all internal tensors fp16) -----------------------
__device__ __half g_xh  [CB * CN * CD];
__device__ __half g_wqh [CD * CP];
__device__ __half g_woh [CD * CD];
__device__ __half g_qkv [CB * CN * CP];
__device__ __half g_ql  [CB * CH * CM * CDH];
__device__ __half g_kl  [CB * CH * CM * CDH];
__device__ __half g_a2  [CB * CH * CM * CM];
__device__ __half g_z0  [CB * CH * CM * CM];
__device__ __half g_z1  [CB * CH * CM * CM];
__device__ __half g_xz  [CB * CH * CM * CM];
__device__ __half g_tt  [CB * CH * CM * CM];
__device__ __half g_uu  [CB * CH * CM * CM];
__device__ __half g_t2  [CB * CH * CM * CDH];
__device__ __half g_zt2 [CB * CH * CM * CDH];
__device__ __half g_oh  [CB * CN * CD];
__device__ unsigned g_scal[2];

// ---------------- helpers ----------------------------------------------------
__device__ __forceinline__ uint32_t h2pack(float lo, float hi) {
    __half2 h = __floats2half2_rn(lo, hi);
    return *reinterpret_cast<uint32_t*>(&h);
}

__device__ __forceinline__ void mma_f16(float* c, const uint32_t* a, const uint32_t* b) {
    asm volatile(
        "mma.sync.aligned.m16n8k16.row.col.f32.f16.f16.f32 "
        "{%0,%1,%2,%3}, {%4,%5,%6,%7}, {%8,%9}, {%0,%1,%2,%3};\n"
        : "+f"(c[0]), "+f"(c[1]), "+f"(c[2]), "+f"(c[3])
        : "r"(a[0]), "r"(a[1]), "r"(a[2]), "r"(a[3]), "r"(b[0]), "r"(b[1]));
}

__device__ __forceinline__ void cp16(void* smem_dst, const void* gsrc) {
    uint32_t d = (uint32_t)__cvta_generic_to_shared(smem_dst);
    asm volatile("cp.async.cg.shared.global [%0], [%1], 16;\n" :: "r"(d), "l"(gsrc));
}

#define LDMX4(r0, r1, r2, r3, addr) \
    asm volatile("ldmatrix.sync.aligned.m8n8.x4.shared.b16 {%0,%1,%2,%3}, [%4];" \
                 : "=r"(r0), "=r"(r1), "=r"(r2), "=r"(r3) : "r"(addr))
#define LDMX4T(r0, r1, r2, r3, addr) \
    asm volatile("ldmatrix.sync.aligned.m8n8.x4.trans.shared.b16 {%0,%1,%2,%3}, [%4];" \
                 : "=r"(r0), "=r"(r1), "=r"(r2), "=r"(r3) : "r"(addr))

// ---------------- fp16 tensor-core batched GEMM (3-stage, dyn smem) ---------
// KT=32. A stride 56 halfs (112B, ldmatrix conflict-free).
// MODE: 0=plain(C half), 1=+bias final (C float), 2=C and D=dc*I-C, 3=only D.
#define KT 32
#define AST 56

template <int BM, int BN, bool TRANSB>
constexpr int gemm_smem_h() {
    return 3 * BM * AST * 2 + (TRANSB ? 3 * BN * AST * 2 : 3 * KT * (BN + 8) * 2);
}

template <int BM, int BN, int WM, int WN, bool TRANSB, int MODE>
__global__ __launch_bounds__(256)
void gemm_h(const __half* __restrict__ A, const __half* __restrict__ B,
            void* __restrict__ Cv, __half* __restrict__ D,
            const float* __restrict__ bias,
            int Kr, int lda, int ldb, int ldc,
            size_t sA1, size_t sA2, size_t sB1, size_t sB2,
            size_t sC1, size_t sC2, float alpha, float dc) {
    constexpr int MF = WM / 16;
    constexpr int NF = WN / 8;
    constexpr int WARPS_N = BN / WN;
    constexpr int BST = BN + 8;   // !TRANSB B stride

    int z = blockIdx.z;
    int zh = z & (CH - 1), zb = z >> 3;
    A += (size_t)zb * sA2 + (size_t)zh * sA1;
    B += (size_t)zb * sB2 + (size_t)zh * sB1;
    __half* C = (__half*)Cv;
    float* Cf = (float*)Cv;
    if (MODE == 1) Cf += (size_t)zb * sC2 + (size_t)zh * sC1;
    else           C  += (size_t)zb * sC2 + (size_t)zh * sC1;
    if (MODE >= 2) D += (size_t)zb * sC2 + (size_t)zh * sC1;

    extern __shared__ __half smh[];
    __half* AsB = smh;                      // [3][BM][AST]
    __half* BsB = smh + 3 * BM * AST;
    uint32_t as_u32 = (uint32_t)__cvta_generic_to_shared(AsB);
    uint32_t bs_u32 = (uint32_t)__cvta_generic_to_shared(BsB);

    int tid = threadIdx.x;
    int m0 = blockIdx.y * BM, n0 = blockIdx.x * BN;
    int wid = tid >> 5, lane = tid & 31;
    int wm = (wid / WARPS_N) * WM;
    int wn = (wid % WARPS_N) * WN;
    int r = lane >> 2, cq = lane & 3;
    int l15 = lane & 15, lhi8 = (lane >> 4) << 3;

    float acc[MF][NF][4] = {};

    auto loadA = [&](int k0, int buf) {
        constexpr int CH8 = BM * KT / 8;
        __half* As = AsB + buf * BM * AST;
#pragma unroll
        for (int c = tid; c < CH8; c += 256) {
            int row = c >> 2, col8 = (c & 3) << 3;
            cp16(&As[row * AST + col8], A + (size_t)(m0 + row) * lda + k0 + col8);
        }
    };
    auto loadB = [&](int k0, int buf) {
        if (TRANSB) {
            constexpr int CH8 = BN * KT / 8;
            __half* Bs = BsB + buf * BN * AST;
#pragma unroll
            for (int c = tid; c < CH8; c += 256) {
                int row = c >> 2, col8 = (c & 3) << 3;
                cp16(&Bs[row * AST + col8], B + (size_t)(n0 + row) * ldb + k0 + col8);
            }
        } else {
            constexpr int CPR = BN / 8;
            constexpr int CH8 = KT * CPR;
            __half* Bs = BsB + buf * KT * BST;
#pragma unroll
            for (int c = tid; c < CH8; c += 256) {
                int row = c / CPR, col8 = (c % CPR) << 3;
                cp16(&Bs[row * BST + col8], B + (size_t)(k0 + row) * ldb + n0 + col8);
            }
        }
    };

    int ntile = Kr / KT;
    loadA(0, 0); loadB(0, 0);
    asm volatile("cp.async.commit_group;\n");
    if (ntile > 1) {
        loadA(KT, 1); loadB(KT, 1);
        asm volatile("cp.async.commit_group;\n");
    }

    for (int t = 0; t < ntile; t++) {
        int buf = t % 3;
        if (t + 2 < ntile) {
            loadA((t + 2) * KT, (t + 2) % 3);
            loadB((t + 2) * KT, (t + 2) % 3);
            asm volatile("cp.async.commit_group;\n");
        }
        int rem = ntile - 1 - t;
        if (rem >= 2)      asm volatile("cp.async.wait_group 2;\n");
        else if (rem == 1) asm volatile("cp.async.wait_group 1;\n");
        else               asm volatile("cp.async.wait_group 0;\n");
        __syncthreads();

        uint32_t a_u = as_u32 + (uint32_t)(buf * BM * AST) * 2;
        uint32_t b_u = TRANSB ? bs_u32 + (uint32_t)(buf * BN * AST) * 2
                              : bs_u32 + (uint32_t)(buf * KT * BST) * 2;
#pragma unroll
        for (int kg = 0; kg < KT; kg += 16) {
            uint32_t afr[MF][4], bfr[NF][2];
#pragma unroll
            for (int mf = 0; mf < MF; mf++) {
                uint32_t addr = a_u + (uint32_t)((wm + mf * 16 + l15) * AST + kg + lhi8) * 2;
                LDMX4(afr[mf][0], afr[mf][1], afr[mf][2], afr[mf][3], addr);
            }
#pragma unroll
            for (int pr = 0; pr < NF / 2; pr++) {
                if (TRANSB) {
                    uint32_t addr = b_u + (uint32_t)((wn + pr * 16 + l15) * AST + kg + lhi8) * 2;
                    LDMX4(bfr[2 * pr][0], bfr[2 * pr + 1][0],
                          bfr[2 * pr][1], bfr[2 * pr + 1][1], addr);
                } else {
                    uint32_t addr = b_u + (uint32_t)((kg + l15) * BST + wn + pr * 16 + lhi8) * 2;
                    LDMX4T(bfr[2 * pr][0], bfr[2 * pr][1],
                           bfr[2 * pr + 1][0], bfr[2 * pr + 1][1], addr);
                }
            }
#pragma unroll
            for (int mf = 0; mf < MF; mf++)
#pragma unroll
                for (int nf = 0; nf < NF; nf++)
                    mma_f16(acc[mf][nf], afr[mf], bfr[nf]);
        }
        __syncthreads();
    }

#pragma unroll
    for (int mf = 0; mf < MF; mf++) {
#pragma unroll
        for (int h = 0; h < 2; h++) {
            int row = m0 + wm + mf * 16 + r + h * 8;
#pragma unroll
            for (int nf = 0; nf < NF; nf++) {
                int col = n0 + wn + nf * 8 + 2 * cq;
                float v0 = acc[mf][nf][2 * h] * alpha;
                float v1 = acc[mf][nf][2 * h + 1] * alpha;
                if (MODE == 1) {
                    v0 += bias[col]; v1 += bias[col + 1];
                    *(float2*)&Cf[(size_t)row * ldc + col] = make_float2(v0, v1);
                } else if (MODE <= 2) {
                    *(uint32_t*)&C[(size_t)row * ldc + col] = h2pack(v0, v1);
                }
                if (MODE >= 2) {
                    float d0 = (row == col     ? dc : 0.f) - v0;
                    float d1 = (row == col + 1 ? dc : 0.f) - v1;
                    *(uint32_t*)&D[(size_t)row * ldc + col] = h2pack(d0, d1);
                }
            }
        }
    }
}

// ---------------- fp16 flash attention --------------------------------------
template <int NW>
__global__ __launch_bounds__(NW * 32, 2)
void flash_h(const __half* __restrict__ Q, int ldq, size_t sQ1, size_t sQ2,
             const __half* __restrict__ K, int ldk, size_t sK1, size_t sK2,
             const __half* __restrict__ V, int ldv, size_t sV1, size_t sV2,
             __half* __restrict__ O, int ldo, size_t sO1, size_t sO2,
             int nkeys, float alpha) {
    extern __shared__ __half smh[];
    __half* KsB = smh;                 // [2][64][72]
    __half* VsB = smh + 2 * 64 * 72;
    constexpr int NT = NW * 32;
    uint32_t ks_u32 = (uint32_t)__cvta_generic_to_shared(KsB);
    uint32_t vs_u32 = (uint32_t)__cvta_generic_to_shared(VsB);

    int z = blockIdx.z;
    int zh = z & 7, zb = z >> 3;
    Q += (size_t)zb * sQ2 + (size_t)zh * sQ1;
    K += (size_t)zb * sK2 + (size_t)zh * sK1;
    V += (size_t)zb * sV2 + (size_t)zh * sV1;
    O += (size_t)zb * sO2 + (size_t)zh * sO1;

    int tid = threadIdx.x, wid = tid >> 5, lane = tid & 31;
    int r = lane >> 2, cq = lane & 3;
    int l15 = lane & 15, lhi8 = (lane >> 4) << 3;
    int qbase = blockIdx.x * (NW * 16);
    int wm = wid * 16;

    uint32_t aq[4][4];
    {
        const __half* q0 = Q + (size_t)(qbase + wm + r) * ldq;
        const __half* q1 = Q + (size_t)(qbase + wm + r + 8) * ldq;
#pragma unroll
        for (int kt = 0; kt < 4; kt++) {
            aq[kt][0] = *(const uint32_t*)&q0[kt * 16 + 2 * cq];
            aq[kt][1] = *(const uint32_t*)&q1[kt * 16 + 2 * cq];
            aq[kt][2] = *(const uint32_t*)&q0[kt * 16 + 8 + 2 * cq];
            aq[kt][3] = *(const uint32_t*)&q1[kt * 16 + 8 + 2 * cq];
        }
    }

    float m0 = -1e30f, m1 = -1e30f, l0 = 0.f, l1 = 0.f;
    float acc_o[8][4] = {};

    auto loadKV = [&](int key0, int buf) {
#pragma unroll
        for (int c = tid; c < 512; c += NT) {
            int row = c >> 3, col8 = (c & 7) << 3;
            cp16(&KsB[buf * 64 * 72 + row * 72 + col8], K + (size_t)(key0 + row) * ldk + col8);
            cp16(&VsB[buf * 64 * 72 + row * 72 + col8], V + (size_t)(key0 + row) * ldv + col8);
        }
    };

    int nchunks = nkeys >> 6;
    loadKV(0, 0);
    asm volatile("cp.async.commit_group;\n");

    for (int ch = 0; ch < nchunks; ch++) {
        int buf = ch & 1;
        if (ch + 1 < nchunks) {
            loadKV((ch + 1) * 64, buf ^ 1);
            asm volatile("cp.async.commit_group;\n");
            asm volatile("cp.async.wait_group 1;\n");
        } else {
            asm volatile("cp.async.wait_group 0;\n");
        }
        __syncthreads();

        uint32_t kb_u = ks_u32 + (uint32_t)(buf * 64 * 72) * 2;
        uint32_t vb_u = vs_u32 + (uint32_t)(buf * 64 * 72) * 2;

        float p[8][4];
#pragma unroll
        for (int nf = 0; nf < 8; nf++)
            p[nf][0] = p[nf][1] = p[nf][2] = p[nf][3] = 0.f;
#pragma unroll
        for (int kt = 0; kt < 4; kt++) {
#pragma unroll
            for (int pr = 0; pr < 4; pr++) {
                uint32_t b2[2][2];
                uint32_t addr = kb_u + (uint32_t)((pr * 16 + l15) * 72 + kt * 16 + lhi8) * 2;
                LDMX4(b2[0][0], b2[1][0], b2[0][1], b2[1][1], addr);
                mma_f16(p[2 * pr],     aq[kt], b2[0]);
                mma_f16(p[2 * pr + 1], aq[kt], b2[1]);
            }
        }
        float mx0 = -1e30f, mx1 = -1e30f;
#pragma unroll
        for (int nf = 0; nf < 8; nf++) {
            p[nf][0] *= alpha; p[nf][1] *= alpha; p[nf][2] *= alpha; p[nf][3] *= alpha;
            mx0 = fmaxf(mx0, fmaxf(p[nf][0], p[nf][1]));
            mx1 = fmaxf(mx1, fmaxf(p[nf][2], p[nf][3]));
        }
        mx0 = fmaxf(mx0, __shfl_xor_sync(~0u, mx0, 1));
        mx0 = fmaxf(mx0, __shfl_xor_sync(~0u, mx0, 2));
        mx1 = fmaxf(mx1, __shfl_xor_sync(~0u, mx1, 1));
        mx1 = fmaxf(mx1, __shfl_xor_sync(~0u, mx1, 2));
        float nm0 = fmaxf(m0, mx0), nm1 = fmaxf(m1, mx1);
        float f0 = __expf(m0 - nm0), f1 = __expf(m1 - nm1);
        m0 = nm0; m1 = nm1;
        float s0 = 0.f, s1 = 0.f;
#pragma unroll
        for (int nf = 0; nf < 8; nf++) {
            p[nf][0] = __expf(p[nf][0] - m0);
            p[nf][1] = __expf(p[nf][1] - m0);
            p[nf][2] = __expf(p[nf][2] - m1);
            p[nf][3] = __expf(p[nf][3] - m1);
            s0 += p[nf][0] + p[nf][1];
            s1 += p[nf][2] + p[nf][3];
        }
        s0 += __shfl_xor_sync(~0u, s0, 1); s0 += __shfl_xor_sync(~0u, s0, 2);
        s1 += __shfl_xor_sync(~0u, s1, 1); s1 += __shfl_xor_sync(~0u, s1, 2);
        l0 = l0 * f0 + s0;
        l1 = l1 * f1 + s1;
#pragma unroll
        for (int nf = 0; nf < 8; nf++) {
            acc_o[nf][0] *= f0; acc_o[nf][1] *= f0;
            acc_o[nf][2] *= f1; acc_o[nf][3] *= f1;
        }

#pragma unroll
        for (int kt = 0; kt < 4; kt++) {
            uint32_t a[4];
            a[0] = h2pack(p[2 * kt][0],     p[2 * kt][1]);
            a[1] = h2pack(p[2 * kt][2],     p[2 * kt][3]);
            a[2] = h2pack(p[2 * kt + 1][0], p[2 * kt + 1][1]);
            a[3] = h2pack(p[2 * kt + 1][2], p[2 * kt + 1][3]);
#pragma unroll
            for (int pr = 0; pr < 4; pr++) {
                uint32_t b2[2][2];
                uint32_t addr = vb_u + (uint32_t)((kt * 16 + l15) * 72 + pr * 16 + lhi8) * 2;
                LDMX4T(b2[0][0], b2[0][1], b2[1][0], b2[1][1], addr);
                mma_f16(acc_o[2 * pr],     a, b2[0]);
                mma_f16(acc_o[2 * pr + 1], a, b2[1]);
            }
        }
        __syncthreads();
    }

    float inv0 = 1.f / l0, inv1 = 1.f / l1;
    int row0 = qbase + wm + r, row1 = row0 + 8;
#pragma unroll
    for (int nf = 0; nf < 8; nf++) {
        int col = nf * 8 + 2 * cq;
        *(uint32_t*)&O[(size_t)row0 * ldo + col] =
            h2pack(acc_o[nf][0] * inv0, acc_o[nf][1] * inv0);
        *(uint32_t*)&O[(size_t)row1 * ldo + col] =
            h2pack(acc_o[nf][2] * inv1, acc_o[nf][3] * inv1);
    }
}

// ---------------- fp32 -> fp16 input conversion ------------------------------
__global__ void f2h_k(const float* __restrict__ s, __half* __restrict__ d) {
    int i = blockIdx.x * blockDim.x + threadIdx.x;
    float4 v = ((const float4*)s)[i];
    uint2 o;
    o.x = h2pack(v.x, v.y);
    o.y = h2pack(v.z, v.w);
    ((uint2*)d)[i] = o;
}

// ---------------- landmarks --------------------------------------------------
__global__ void landmark_k() {
    int idx = blockIdx.x * blockDim.x + threadIdx.x;
    if (idx >= CB * CH * CM * CDH) return;
    int d = idx & 63;
    int m = (idx >> 6) & (CM - 1);
    int h = (idx >> 14) & (CH - 1);
    int b = idx >> 17;
    const __half* base = g_qkv + ((size_t)(b * CN + m * CL)) * CP + h * CDH + d;
    float sq = 0.f, sk = 0.f;
#pragma unroll
    for (int j = 0; j < CL; j++) {
        sq += __half2float(base[(size_t)j * CP]);
        sk += __half2float(base[(size_t)j * CP + CD]);
    }
    g_ql[idx] = __float2half(sq * (CSCALE / CL));
    g_kl[idx] = __float2half(sk * (1.0f / CL));
}

// ---------------- softmax (half rows of 256) ---------------------------------
__global__ void softmax256_k(__half* __restrict__ data) {
    int row = blockIdx.x * 8 + (threadIdx.x >> 5);
    int lane = threadIdx.x & 31;
    uint4* pv = (uint4*)(data + (size_t)row * 256);
    uint4 u = pv[lane];
    __half2* hs = (__half2*)&u;
    float f[8];
#pragma unroll
    for (int i = 0; i < 4; i++) {
        float2 ff = __half22float2(hs[i]);
        f[2 * i] = ff.x; f[2 * i + 1] = ff.y;
    }
    float mx = -3.4e38f;
#pragma unroll
    for (int i = 0; i < 8; i++) mx = fmaxf(mx, f[i]);
#pragma unroll
    for (int s = 16; s > 0; s >>= 1) mx = fmaxf(mx, __shfl_xor_sync(~0u, mx, s));
    float sum = 0.f;
#pragma unroll
    for (int i = 0; i < 8; i++) { f[i] = __expf(f[i] - mx); sum += f[i]; }
#pragma unroll
    for (int s = 16; s > 0; s >>= 1) sum += __shfl_xor_sync(~0u, sum, s);
    float inv = 1.f / sum;
#pragma unroll
    for (int i = 0; i < 4; i++)
        hs[i] = __floats2half2_rn(f[2 * i] * inv, f[2 * i + 1] * inv);
    pv[lane] = u;
}

// ---------------- pinv scaling ---------------------------------------------
__global__ void pinv_scal_init() { if (threadIdx.x < 2) g_scal[threadIdx.x] = 0u; }

__global__ void pinv_scal_k() {
    const __half* a = g_a2 + (size_t)blockIdx.x * CM * CM;
    int t = threadIdx.x;
    float cs = 0.f, rs = 0.f;
    for (int i = 0; i < CM; i++) {
        cs += fabsf(__half2float(a[i * CM + t]));
        rs += fabsf(__half2float(a[t * CM + i]));
    }
    __shared__ float sh[256];
    sh[t] = rs; __syncthreads();
    for (int s = 128; s > 0; s >>= 1) { if (t < s) sh[t] = fmaxf(sh[t], sh[t + s]); __syncthreads(); }
    if (t == 0) atomicMax(&g_scal[0], __float_as_uint(sh[0]));
    __syncthreads();
    sh[t] = cs; __syncthreads();
    for (int s = 128; s > 0; s >>= 1) { if (t < s) sh[t] = fmaxf(sh[t], sh[t + s]); __syncthreads(); }
    if (t == 0) atomicMax(&g_scal[1], __float_as_uint(sh[0]));
}

__global__ void zinit_k() {
    int idx = blockIdx.x * blockDim.x + threadIdx.x;
    if (idx >= CB * CH * CM * CM) return;
    float inv = 1.f / (__uint_as_float(g_scal[0]) * __uint_as_float(g_scal[1]));
    int z = idx >> 16;
    int im = idx & 65535;
    int i = im >> 8, j = im & 255;
    g_z0[(size_t)z * 65536 + j * 256 + i] = __float2half(__half2float(g_a2[idx]) * inv);
}

// ---------------- host ------------------------------------------------------
extern "C" void kernel_launch(void* const* d_in, const int* in_sizes, int n_in,
                              void* d_out, int out_size) {
    const float* x     = (const float*)d_in[0];
    const float* w_qkv = (const float*)d_in[1];
    const float* w_out = (const float*)d_in[2];
    const float* b_out = (const float*)d_in[3];
    float* out = (float*)d_out;

    constexpr int SM_NN  = gemm_smem_h<128, 128, false>();
    constexpr int SM_NT  = gemm_smem_h<128, 128, true>();
    constexpr int SM_N64 = gemm_smem_h<128, 64, false>();
    const int FLASH_SMEM = 2 * 2 * 64 * 72 * 2;

    static __half *p_xh = nullptr, *p_wqh, *p_woh, *p_qkv, *p_ql, *p_kl, *p_a2,
                  *p_z0, *p_z1, *p_xz, *p_tt, *p_uu, *p_t2, *p_zt2, *p_oh;
    static cudaStream_t s1;
    static cudaEvent_t evFork, evJoin;
    if (!p_xh) {
        cudaGetSymbolAddress((void**)&p_xh,   g_xh);
        cudaGetSymbolAddress((void**)&p_wqh,  g_wqh);
        cudaGetSymbolAddress((void**)&p_woh,  g_woh);
        cudaGetSymbolAddress((void**)&p_qkv,  g_qkv);
        cudaGetSymbolAddress((void**)&p_ql,   g_ql);
        cudaGetSymbolAddress((void**)&p_kl,   g_kl);
        cudaGetSymbolAddress((void**)&p_a2,   g_a2);
        cudaGetSymbolAddress((void**)&p_z0,   g_z0);
        cudaGetSymbolAddress((void**)&p_z1,   g_z1);
        cudaGetSymbolAddress((void**)&p_xz,   g_xz);
        cudaGetSymbolAddress((void**)&p_tt,   g_tt);
        cudaGetSymbolAddress((void**)&p_uu,   g_uu);
        cudaGetSymbolAddress((void**)&p_t2,   g_t2);
        cudaGetSymbolAddress((void**)&p_zt2,  g_zt2);
        cudaGetSymbolAddress((void**)&p_oh,   g_oh);
        cudaStreamCreateWithFlags(&s1, cudaStreamNonBlocking);
        cudaEventCreateWithFlags(&evFork, cudaEventDisableTiming);
        cudaEventCreateWithFlags(&evJoin, cudaEventDisableTiming);
        cudaFuncSetAttribute(flash_h<8>, cudaFuncAttributeMaxDynamicSharedMemorySize, FLASH_SMEM);
        cudaFuncSetAttribute((const void*)gemm_h<128, 128, 64, 32, false, 0>,
                             cudaFuncAttributeMaxDynamicSharedMemorySize, SM_NN);
        cudaFuncSetAttribute((const void*)gemm_h<128, 128, 64, 32, false, 1>,
                             cudaFuncAttributeMaxDynamicSharedMemorySize, SM_NN);
        cudaFuncSetAttribute((const void*)gemm_h<128, 128, 64, 32, false, 2>,
                             cudaFuncAttributeMaxDynamicSharedMemorySize, SM_NN);
        cudaFuncSetAttribute((const void*)gemm_h<128, 128, 64, 32, false, 3>,
                             cudaFuncAttributeMaxDynamicSharedMemorySize, SM_NN);
        cudaFuncSetAttribute((const void*)gemm_h<128, 128, 64, 32, true, 0>,
                             cudaFuncAttributeMaxDynamicSharedMemorySize, SM_NT);
        cudaFuncSetAttribute((const void*)gemm_h<128, 64, 32, 32, false, 0>,
                             cudaFuncAttributeMaxDynamicSharedMemorySize, SM_N64);
    }

    const size_t sQKVh = CDH;
    const size_t sQKVb = (size_t)CN * CP;
    const size_t sLMh  = (size_t)CM * CDH;
    const size_t sMM   = (size_t)CM * CM;
    const size_t sT2   = (size_t)CM * CDH;

    // 0) input conversion (w_out on s1)
    f2h_k<<<(CB * CN * CD) / 1024, 256>>>(x, p_xh);
    f2h_k<<<(CD * CP) / 1024, 256>>>(w_qkv, p_wqh);
    f2h_k<<<(CD * CD) / 1024, 256, 0, s1>>>(w_out, p_woh);

    // 1) qkv = x @ w_qkv
    gemm_h<128, 128, 64, 32, false, 0>
        <<<dim3(CP / 128, (CB * CN) / 128, 1), 256, SM_NN>>>(
        p_xh, p_wqh, p_qkv, nullptr, nullptr, CD, CD, CP, CP,
        0, 0, 0, 0, 0, 0, 1.f, 0.f);

    // 2) landmarks
    landmark_k<<<(CB * CH * CM * CDH) / 256, 256>>>();

    // ---- fork: F1 on s1, concurrent with pinv pipeline
    cudaEventRecord(evFork, 0);
    cudaStreamWaitEvent(s1, evFork, 0);
    flash_h<8><<<dim3(CM / 128, 1, CB * CH), 256, FLASH_SMEM, s1>>>(
        p_ql, CDH, sLMh, CH * sLMh,
        p_qkv + CD, CP, sQKVh, sQKVb,
        p_qkv + 2 * CD, CP, sQKVh, sQKVb,
        p_t2, CDH, sT2, CH * sT2,
        CN, 1.f);
    cudaEventRecord(evJoin, s1);

    // 3) sim2 = ql @ kl^T ; softmax
    gemm_h<128, 128, 64, 32, true, 0>
        <<<dim3(CM / 128, CM / 128, CB * CH), 256, SM_NT>>>(
        p_ql, p_kl, p_a2, nullptr, nullptr, CDH, CDH, CDH, CM,
        sLMh, CH * sLMh, sLMh, CH * sLMh, sMM, CH * sMM, 1.f, 0.f);
    softmax256_k<<<(CB * CH * CM) / 8, 256>>>(p_a2);

    // 5) pinv init
    pinv_scal_init<<<1, 32>>>();
    pinv_scal_k<<<CB * CH, 256>>>();
    zinit_k<<<(CB * CH * CM * CM) / 256, 256>>>();

    // 6) Newton-Schulz iterations (128x128 tiles — proven best)
    dim3 gMM(CM / 128, CM / 128, CB * CH);
    __half* zin = p_z0;
    __half* zout = p_z1;
    for (int it = 0; it < CITERS; it++) {
        gemm_h<128, 128, 64, 32, false, 2><<<gMM, 256, SM_NN>>>(
            p_a2, zin, p_xz, p_tt, nullptr, CM, CM, CM, CM,
            sMM, CH * sMM, sMM, CH * sMM, sMM, CH * sMM, 1.f, 7.f);
        gemm_h<128, 128, 64, 32, false, 3><<<gMM, 256, SM_NN>>>(
            p_xz, p_tt, nullptr, p_uu, nullptr, CM, CM, CM, CM,
            sMM, CH * sMM, sMM, CH * sMM, sMM, CH * sMM, 1.f, 15.f);
        gemm_h<128, 128, 64, 32, false, 3><<<gMM, 256, SM_NN>>>(
            p_xz, p_uu, nullptr, p_tt, nullptr, CM, CM, CM, CM,
            sMM, CH * sMM, sMM, CH * sMM, sMM, CH * sMM, 1.f, 13.f);
        gemm_h<128, 128, 64, 32, false, 0><<<gMM, 256, SM_NN>>>(
            zin, p_tt, zout, nullptr, nullptr, CM, CM, CM, CM,
            sMM, CH * sMM, sMM, CH * sMM, sMM, CH * sMM, 0.25f, 0.f);
        __half* tmp = zin; zin = zout; zout = tmp;
    }

    // ---- join: t2 ready
    cudaStreamWaitEvent(0, evJoin, 0);

    // 7) zt2 = z @ t2
    gemm_h<128, 64, 32, 32, false, 0>
        <<<dim3(1, CM / 128, CB * CH), 256, SM_N64>>>(
        zin, p_t2, p_zt2, nullptr, nullptr, CM, CM, CDH, CDH,
        sMM, CH * sMM, sT2, CH * sT2, sT2, CH * sT2, 1.f, 0.f);

    // 8) F2: oh = softmax(SCALE * q @ kl^T) @ zt2  -> [b,n,h*dh]
    flash_h<8><<<dim3(CN / 128, 1, CB * CH), 256, FLASH_SMEM>>>(
        p_qkv, CP, sQKVh, sQKVb,
        p_kl, CDH, sLMh, CH * sLMh,
        p_zt2, CDH, sT2, CH * sT2,
        p_oh, CD, (size_t)CDH, (size_t)CN * CD,
        CM, CSCALE);

    // 9) out = oh @ w_out + b_out   (fp32 output)
    gemm_h<128, 128, 64, 32, false, 1>
        <<<dim3(CD / 128, (CB * CN) / 128, 1), 256, SM_NN>>>(
        p_oh, p_woh, out, nullptr, b_out, CD, CD, CD, CD,
        0, 0, 0, 0, 0, 0, 1.f, 0.f);
}